// round 9
// baseline (speedup 1.0000x reference)
#include <cuda_runtime.h>
#include <cuda_bf16.h>
#include <cstddef>

// Problem constants: N=50000, DEG=32, E=N*32, F=64, K=3, DIM=2, L=3
#define MAXN 50000
#define FDIM 64
#define KF   192        // K * F
#define TILE 64

// smem: gs[64][192] row-major + wf4[8][64] float4 staging (A/B node pair)
#define GS_FLOATS (TILE * KF)
#define SMEM_FLOATS (GS_FLOATS + 8 * 64 * 4)
#define SMEM_BYTES  (SMEM_FLOATS * 4)      // 57344 B -> 3 CTAs/SM

__device__ float h_bufA[(size_t)MAXN * FDIM];
__device__ float h_bufB[(size_t)MAXN * FDIM];
// WP[layer][pp][t] float4 = {Wk[2pp][2t], Wk[2pp+1][2t], Wk[2pp][2t+1], Wk[2pp+1][2t+1]}
__device__ float WP_buf[3 * 96 * 32 * 4];

// Packed fp32x2 FMA (sm_103a FFMA2 — only reachable via PTX)
#define FMA_F32X2(d, a, b, c) \
    asm("fma.rn.f32x2 %0, %1, %2, %3;" : "=l"(d) : "l"(a), "l"(b), "l"(c))
#define PACK_DUP(d, x) \
    asm("mov.b64 %0, {%1, %1};" : "=l"(d) : "f"(x))
#define UNPACK2(lo, hi, v) \
    asm("mov.b64 {%0, %1}, %2;" : "=f"(lo), "=f"(hi) : "l"(v))

typedef unsigned long long ull;

// ---------------------------------------------------------------------------
// Prep: rearrange fcW into WP layout (K-pair-packed, warp-coalesced).
//   Wk[p][c] = fcW[j*192 + k*64 + c],  p = k*64 + j
// ---------------------------------------------------------------------------
__global__ void prep_kernel(const float* __restrict__ fcW, int nL)
{
    const int idx = blockIdx.x * 256 + threadIdx.x;
    const int total = nL * 96 * 32;
    if (idx >= total) return;
    const int i  = idx / (96 * 32);
    const int rem = idx - i * 96 * 32;
    const int pp = rem >> 5, t = rem & 31;
    const float* W = fcW + i * 64 * 192;
    const int p0 = 2 * pp, p1 = 2 * pp + 1;
    const int k0 = p0 >> 6, j0 = p0 & 63;
    const int k1 = p1 >> 6, j1 = p1 & 63;
    float4 v;
    v.x = W[j0 * 192 + k0 * 64 + 2 * t];
    v.y = W[j1 * 192 + k1 * 64 + 2 * t];
    v.z = W[j0 * 192 + k0 * 64 + 2 * t + 1];
    v.w = W[j1 * 192 + k1 * 64 + 2 * t + 1];
    ((float4*)WP_buf)[idx] = v;
}

// ---------------------------------------------------------------------------
// Fused layer kernel. Phase A: dual-node interleaved gather (2x MLP).
// Phase B: block GEMM, g via LDS.128 pp-pairs, W via coalesced LDG (L1).
// ---------------------------------------------------------------------------
__global__ __launch_bounds__(256, 3)
void fused_layer(const float* __restrict__ h,
                 const float* __restrict__ pseudo,   // [E,2]
                 const int*   __restrict__ rowptr,   // [N+1]
                 const int*   __restrict__ colind,   // [E]
                 const float* __restrict__ pW,       // [2,2]
                 const float* __restrict__ pb,       // [2]
                 const float* __restrict__ mu,       // [K,2]
                 const float* __restrict__ isg,      // [K,2]
                 const float* __restrict__ WP,       // [96][32] float4
                 float* __restrict__ out, int n)
{
    extern __shared__ float smem[];
    float* gs = smem;                               // [64][192]
    float4* wf4 = (float4*)(smem + GS_FLOATS);      // [8][64]

    const int tid = threadIdx.x;
    const int wid = tid >> 5;
    const int lid = tid & 31;

    const float2* __restrict__ ps2 = (const float2*)pseudo;
    const ulonglong2* __restrict__ wpv = (const ulonglong2*)WP;

    // phase-B mapping
    const int tx = tid & 31;   // cols 2tx, 2tx+1
    const int ty = tid >> 5;   // rows 8ty .. +7

    const int ntiles = (n + TILE - 1) / TILE;
    for (int tile = blockIdx.x; tile < ntiles; tile += gridDim.x) {
        const int r0 = tile * TILE;
        const int rows = min(TILE, n - r0);
        __syncthreads();   // prev phase-B readers done

        // ---------------- Phase A: dual-node aggregation ------------------
        {
            const float W00 = __ldg(&pW[0]), W01 = __ldg(&pW[1]);
            const float W10 = __ldg(&pW[2]), W11 = __ldg(&pW[3]);
            const float b0 = __ldg(&pb[0]), b1 = __ldg(&pb[1]);
            const float m00 = __ldg(&mu[0]), m01 = __ldg(&mu[1]);
            const float m10 = __ldg(&mu[2]), m11 = __ldg(&mu[3]);
            const float m20 = __ldg(&mu[4]), m21 = __ldg(&mu[5]);
            float q0 = __ldg(&isg[0]), q1 = __ldg(&isg[1]);
            const float s00 = q0*q0, s01 = q1*q1;
            q0 = __ldg(&isg[2]); q1 = __ldg(&isg[3]);
            const float s10 = q0*q0, s11 = q1*q1;
            q0 = __ldg(&isg[4]); q1 = __ldg(&isg[5]);
            const float s20 = q0*q0, s21 = q1*q1;

            float4* wfA = wf4 + (wid << 6);
            float4* wfB = wfA + 32;

            for (int jp = 0; jp < 4; jp++) {
                const int rA = (wid << 3) + (jp << 1);
                const int nodeA = r0 + rA;
                if (nodeA >= n) break;
                const int nodeB = nodeA + 1;
                const bool hasB = (nodeB < n);

                int bA = rowptr[nodeA];
                const int eA = rowptr[nodeA + 1];
                int bB = hasB ? rowptr[nodeB] : 0;
                const int eB = hasB ? rowptr[nodeB + 1] : 0;

                ull A0 = 0ULL, A1 = 0ULL, A2 = 0ULL;
                ull B0 = 0ULL, B1 = 0ULL, B2 = 0ULL;

                while (bA < eA || bB < eB) {
                    int cA = eA - bA; cA = cA < 0 ? 0 : (cA > 32 ? 32 : cA);
                    int cB = eB - bB; cB = cB < 0 ? 0 : (cB > 32 ? 32 : cB);

                    if (lid < cA) {
                        const int e = bA + lid;
                        float2 ps = __ldg(&ps2[e]);
                        float u0 = tanhf(fmaf(ps.y, W10, fmaf(ps.x, W00, b0)));
                        float u1 = tanhf(fmaf(ps.y, W11, fmaf(ps.x, W01, b1)));
                        float d0 = u0 - m00, d1 = u1 - m01;
                        float w0 = __expf(-0.5f * (d0*d0*s00 + d1*d1*s01));
                        d0 = u0 - m10; d1 = u1 - m11;
                        float w1 = __expf(-0.5f * (d0*d0*s10 + d1*d1*s11));
                        d0 = u0 - m20; d1 = u1 - m21;
                        float w2 = __expf(-0.5f * (d0*d0*s20 + d1*d1*s21));
                        wfA[lid] = make_float4(w0, w1, w2,
                                               __int_as_float(__ldg(&colind[e])));
                    }
                    if (lid < cB) {
                        const int e = bB + lid;
                        float2 ps = __ldg(&ps2[e]);
                        float u0 = tanhf(fmaf(ps.y, W10, fmaf(ps.x, W00, b0)));
                        float u1 = tanhf(fmaf(ps.y, W11, fmaf(ps.x, W01, b1)));
                        float d0 = u0 - m00, d1 = u1 - m01;
                        float w0 = __expf(-0.5f * (d0*d0*s00 + d1*d1*s01));
                        d0 = u0 - m10; d1 = u1 - m11;
                        float w1 = __expf(-0.5f * (d0*d0*s10 + d1*d1*s11));
                        d0 = u0 - m20; d1 = u1 - m21;
                        float w2 = __expf(-0.5f * (d0*d0*s20 + d1*d1*s21));
                        wfB[lid] = make_float4(w0, w1, w2,
                                               __int_as_float(__ldg(&colind[e])));
                    }
                    __syncwarp();

                    const int m = cA > cB ? cA : cB;
                    #pragma unroll 4
                    for (int t = 0; t < m; t++) {
                        if (t < cA) {
                            const float4 wt = wfA[t];
                            const int src = __float_as_int(wt.w);
                            const ull hv = *(const ull*)(h + (size_t)src * FDIM + 2 * lid);
                            ull w0d, w1d, w2d;
                            PACK_DUP(w0d, wt.x); PACK_DUP(w1d, wt.y); PACK_DUP(w2d, wt.z);
                            FMA_F32X2(A0, hv, w0d, A0);
                            FMA_F32X2(A1, hv, w1d, A1);
                            FMA_F32X2(A2, hv, w2d, A2);
                        }
                        if (t < cB) {
                            const float4 wt = wfB[t];
                            const int src = __float_as_int(wt.w);
                            const ull hv = *(const ull*)(h + (size_t)src * FDIM + 2 * lid);
                            ull w0d, w1d, w2d;
                            PACK_DUP(w0d, wt.x); PACK_DUP(w1d, wt.y); PACK_DUP(w2d, wt.z);
                            FMA_F32X2(B0, hv, w0d, B0);
                            FMA_F32X2(B1, hv, w1d, B1);
                            FMA_F32X2(B2, hv, w2d, B2);
                        }
                    }
                    __syncwarp();
                    bA += cA; bB += cB;
                }

                *(ull*)(gs + rA * KF + 2 * lid      ) = A0;
                *(ull*)(gs + rA * KF + 2 * lid +  64) = A1;
                *(ull*)(gs + rA * KF + 2 * lid + 128) = A2;
                if (hasB) {
                    *(ull*)(gs + (rA + 1) * KF + 2 * lid      ) = B0;
                    *(ull*)(gs + (rA + 1) * KF + 2 * lid +  64) = B1;
                    *(ull*)(gs + (rA + 1) * KF + 2 * lid + 128) = B2;
                }
            }
        }
        __syncthreads();

        // ---------------- Phase B: GEMM -----------------------------------
        {
            const ull* gp = (const ull*)(gs + (ty << 3) * KF);

            ull acc[8][2];
            #pragma unroll
            for (int i = 0; i < 8; i++) { acc[i][0] = 0ULL; acc[i][1] = 0ULL; }

            #pragma unroll 2
            for (int pp2 = 0; pp2 < 48; pp2++) {
                const ulonglong2 wA = __ldg(&wpv[(2 * pp2    ) * 32 + tx]);
                const ulonglong2 wB = __ldg(&wpv[(2 * pp2 + 1) * 32 + tx]);
                #pragma unroll
                for (int i = 0; i < 8; i++) {
                    const ulonglong2 gv = *(const ulonglong2*)(gp + i * 96 + 2 * pp2);
                    FMA_F32X2(acc[i][0], gv.x, wA.x, acc[i][0]);
                    FMA_F32X2(acc[i][1], gv.x, wA.y, acc[i][1]);
                    FMA_F32X2(acc[i][0], gv.y, wB.x, acc[i][0]);
                    FMA_F32X2(acc[i][1], gv.y, wB.y, acc[i][1]);
                }
            }

            #pragma unroll
            for (int i = 0; i < 8; i++) {
                const int r = (ty << 3) + i;
                if (r < rows) {
                    float e0, o0, e1, o1;
                    UNPACK2(e0, o0, acc[i][0]);
                    UNPACK2(e1, o1, acc[i][1]);
                    *(float2*)&out[(size_t)(r0 + r) * FDIM + 2 * tx] =
                        make_float2(e0 + o0, e1 + o1);
                }
            }
        }
    }
}

// ---------------------------------------------------------------------------
extern "C" void kernel_launch(void* const* d_in, const int* in_sizes, int n_in,
                              void* d_out, int out_size)
{
    const float* feat   = (const float*)d_in[0];
    const float* pseudo = (const float*)d_in[1];
    const int*   rowptr = (const int*)  d_in[2];
    const int*   colind = (const int*)  d_in[3];
    const float* projW  = (const float*)d_in[4];  // [L,2,2]
    const float* projb  = (const float*)d_in[5];  // [L,2]
    const float* fcW    = (const float*)d_in[6];  // [L,64,192]
    const float* mu     = (const float*)d_in[7];  // [L,3,2]
    const float* isg    = (const float*)d_in[8];  // [L,3,2]

    const int n  = in_sizes[0] / FDIM;
    const int nL = in_sizes[6] / (FDIM * KF);

    void *hap, *hbp, *wpp;
    cudaGetSymbolAddress(&hap, h_bufA);
    cudaGetSymbolAddress(&hbp, h_bufB);
    cudaGetSymbolAddress(&wpp, WP_buf);
    float* hbufs[2] = { (float*)hap, (float*)hbp };
    const float* WP = (const float*)wpp;

    cudaFuncSetAttribute(fused_layer, cudaFuncAttributeMaxDynamicSharedMemorySize, SMEM_BYTES);

    const int ptotal = nL * 96 * 32;
    prep_kernel<<<(ptotal + 255) / 256, 256>>>(fcW, nL);

    const int ntiles = (n + TILE - 1) / TILE;
    const int grid = ntiles < 444 ? ntiles : 444;   // 3 CTAs/SM persistent

    const float* hin = feat;
    for (int i = 0; i < nL; i++) {
        float* hout = (i == nL - 1) ? (float*)d_out : hbufs[i & 1];
        fused_layer<<<grid, 256, SMEM_BYTES>>>(hin, pseudo, rowptr, colind,
                                               projW + i * 4, projb + i * 2,
                                               mu + i * 6, isg + i * 6,
                                               WP + (size_t)i * 96 * 32 * 4,
                                               hout, n);
        hin = hout;
    }
}